// round 6
// baseline (speedup 1.0000x reference)
#include <cuda_runtime.h>
#include <cuda_fp16.h>
#include <cstdint>
#include <cstddef>

// out = x @ Wv^T + bv.  (Reference's softmax rows sum to 1 => its final
// einsum('btu,btj->btj', weights, v) == v + rounding; Q/K/softmax are dead.)
//
// Single-pass fp16 GEMM M=8192, K=1024, N=64 on portable mma.sync m16n8k16:
//   D = f16(x) * f16(W) with fp32 accumulate; rel_err ~ 2.9e-4 < 1e-3.
// R6: 128 CTAs x 512 threads (16 warps = 4M x 4N, warp m16n16, 4 warps/SMSP).
// W preconverted once to fragment layout (wconv), streamed via 4-stage
// cp.async ring. x: coalesced LDG.128 -> 3-chunk reg ring -> cvt -> fp16 smem
// tile (pitch 24 words, conflict-free LDS.64 frags). One syncthreads/chunk.

#define NEMB    1024
#define NH      64
#define MT      64
#define THREADS 512
#define GRID    128             // 8192 / 64
#define KCH     32              // K per chunk
#define NCH     32              // chunks
#define PW      24              // words per row in x fp16 tile (conflict-free)
#define XTW     (64 * PW)       // words per x buffer (1536)

// W fragments: [chunk 0..31][step 0..1][wn 0..3][lane 0..31] -> uint4
//  .x/.y = b0/b1 of n-tile j=2*wn,  .z/.w = n-tile j=2*wn+1
//  b0 = f16x2{W(n,k),W(n,k+1)}, b1 = f16x2{W(n,k+8),W(n,k+9)},
//  n = j*8 + (lane>>2), k = (chunk*2+step)*16 + (lane&3)*2
__device__ uint4 g_wf[NCH * 2 * 4 * 32];   // 8192 uint4 = 128 KB

__global__ void wconv(const float* __restrict__ W)
{
    int id   = blockIdx.x * blockDim.x + threadIdx.x;   // 0..8191
    int lane = id & 31;
    int wn   = (id >> 5) & 3;
    int st   = (id >> 7) & 1;
    int ch   = id >> 8;
    int s    = ch * 2 + st;
    int k    = s * 16 + (lane & 3) * 2;
    uint4 o;
#pragma unroll
    for (int jj = 0; jj < 2; jj++) {
        int n = (wn * 2 + jj) * 8 + (lane >> 2);
        const float* p = W + (size_t)n * NEMB + k;
        __half2 h0 = __float22half2_rn(make_float2(p[0], p[1]));
        __half2 h1 = __float22half2_rn(make_float2(p[8], p[9]));
        if (jj == 0) { o.x = *(uint32_t*)&h0; o.y = *(uint32_t*)&h1; }
        else         { o.z = *(uint32_t*)&h0; o.w = *(uint32_t*)&h1; }
    }
    g_wf[id] = o;
}

__shared__ __align__(16) uint4 wsm[4][2][4][32];     // 16 KB W ring
__shared__ __align__(16) unsigned int xsm[2 * XTW];  // 12 KB x fp16 tiles
__shared__ float bias_s[NH];

__device__ __forceinline__ void mma16816(float* c,
                                         uint32_t a0, uint32_t a1, uint32_t a2, uint32_t a3,
                                         uint32_t b0, uint32_t b1)
{
    asm volatile(
        "mma.sync.aligned.m16n8k16.row.col.f32.f16.f16.f32 "
        "{%0,%1,%2,%3}, {%4,%5,%6,%7}, {%8,%9}, {%0,%1,%2,%3};"
        : "+f"(c[0]), "+f"(c[1]), "+f"(c[2]), "+f"(c[3])
        : "r"(a0), "r"(a1), "r"(a2), "r"(a3), "r"(b0), "r"(b1));
}

__device__ __forceinline__ void cp16(uint32_t s, const void* g)
{
    asm volatile("cp.async.cg.shared.global [%0], [%1], 16;" :: "r"(s), "l"(g));
}

__global__ void __launch_bounds__(THREADS)
vproj(const float* __restrict__ x, const float* __restrict__ bv,
      float* __restrict__ out)
{
    const int t   = threadIdx.x;
    const int wid = t >> 5;
    const int lid = t & 31;
    const int wm  = wid & 3;          // M slice (16 rows)
    const int wn  = wid >> 2;         // N slice (16 cols = 2 n-tiles)
    const int rowbase = blockIdx.x * MT;

    if (t < 16) ((float4*)bias_s)[t] = ((const float4*)bv)[t];

    const uint32_t wsm_s = (uint32_t)__cvta_generic_to_shared(&wsm[0][0][0][0]);

    // ---- x loader mapping: row = t>>3, q = t&7 (float4 within K32 chunk) ----
    const int lrow = t >> 3;
    const int q    = t & 7;
    const float* xg = x + (size_t)(rowbase + lrow) * NEMB + q * 4;

    // conv target word positions (k-interleaved layout; see pos derivation)
    const int qq  = q & 3;
    const int qst = q >> 2;
    const int pos0 = (qq < 2) ? (qq * 4) : ((qq - 2) * 4 + 1);
    const int convbase = lrow * PW + qst * 8 + pos0;

    // ---- prime pipelines: x reg ring (3 chunks), W cp.async (3 chunks) ----
    float4 xr[3];
    xr[0] = *(const float4*)(xg);
    xr[1] = *(const float4*)(xg + KCH);
    xr[2] = *(const float4*)(xg + 2 * KCH);

#pragma unroll
    for (int c = 0; c < 3; c++) {
        if (t < 256)
            cp16(wsm_s + (uint32_t)(c * 256 + t) * 16, g_wf + c * 256 + t);
        asm volatile("cp.async.commit_group;");
    }

    float acc[2][4] = {{0.f, 0.f, 0.f, 0.f}, {0.f, 0.f, 0.f, 0.f}};

    // A fragment read offset (word index), conflict-free with PW=24
    const int aoff = (wm * 16 + (lid >> 2)) * PW + (lid & 3) * 2;

    int slot = 0;   // c % 3

#pragma unroll 1
    for (int c = 0; c < NCH; c++) {
        // ---- convert held x chunk -> fp16 tile buffer c&1 ----
        {
            float4 f = xr[slot];
            __half2 h0 = __float22half2_rn(make_float2(f.x, f.y));
            __half2 h1 = __float22half2_rn(make_float2(f.z, f.w));
            unsigned int* xb = xsm + (c & 1) * XTW + convbase;
            xb[0] = *(uint32_t*)&h0;
            xb[2] = *(uint32_t*)&h1;
        }

        // ---- refill pipelines for chunk c+3 ----
        if (c + 3 < NCH) {
            xr[slot] = *(const float4*)(xg + (c + 3) * KCH);
            if (t < 256)
                cp16(wsm_s + (uint32_t)((((c + 3) & 3) * 256 + t)) * 16,
                     g_wf + (c + 3) * 256 + t);
        }
        asm volatile("cp.async.commit_group;");
        asm volatile("cp.async.wait_group 2;");
        __syncthreads();

        // ---- compute: 2 k16-steps, 2 n-tiles ----
        const unsigned int* xb = xsm + (c & 1) * XTW;
#pragma unroll
        for (int st = 0; st < 2; st++) {
            uint2 v0 = *(const uint2*)&xb[aoff + st * 8];
            uint2 v1 = *(const uint2*)&xb[aoff + st * 8 + 8 * PW];
            uint4 wq = wsm[c & 3][st][wn][lid];
            mma16816(acc[0], v0.x, v1.x, v0.y, v1.y, wq.x, wq.y);
            mma16816(acc[1], v0.x, v1.x, v0.y, v1.y, wq.z, wq.w);
        }

        slot = (slot == 2) ? 0 : slot + 1;
    }

    // ---- epilogue: add bias, store float2 pairs ----
    const int orow = rowbase + wm * 16 + (lid >> 2);
#pragma unroll
    for (int j = 0; j < 2; j++) {
        const int col = (wn * 2 + j) * 8 + ((lid & 3) << 1);
        const float b0 = bias_s[col], b1 = bias_s[col + 1];
        float2 lo = make_float2(acc[j][0] + b0, acc[j][1] + b1);
        float2 hi = make_float2(acc[j][2] + b0, acc[j][3] + b1);
        *(float2*)(out + (size_t)orow * NH + col)       = lo;
        *(float2*)(out + (size_t)(orow + 8) * NH + col) = hi;
    }
}

extern "C" void kernel_launch(void* const* d_in, const int* in_sizes, int n_in,
                              void* d_out, int out_size)
{
    const float* x  = (const float*)d_in[0];
    const float* Wv = (const float*)d_in[5];
    const float* bv = (const float*)d_in[6];

    wconv<<<32, 256>>>(Wv);
    vproj<<<GRID, THREADS>>>(x, bv, (float*)d_out);
}

// round 7
// speedup vs baseline: 1.0859x; 1.0859x over previous
#include <cuda_runtime.h>
#include <cuda_fp16.h>
#include <cstdint>
#include <cstddef>

// out = x @ Wv^T + bv.  (Reference's softmax rows sum to 1 => its final
// einsum('btu,btj->btj', weights, v) == v + rounding; Q/K/softmax are dead.)
//
// Single-pass fp16 GEMM M=8192, K=1024, N=64 on portable mma.sync m16n8k16:
//   D = f16(x) * f16(W), fp32 accumulate; rel_err ~2.9e-4 (R6-measured) < 1e-3.
// R7 = R6 with the register-ring LOCAL-MEMORY bug fixed: main loop unrolled
// x4 so all ring indices (x regs, smem buffers, W stages) are compile-time
// static. x LDG lead = 4 chunks. 128 CTAs x 512 threads (16 warps, 4M x 4N).

#define NEMB    1024
#define NH      64
#define MT      64
#define THREADS 512
#define GRID    128             // 8192 / 64
#define KCH     32              // K per chunk
#define NCH     32              // chunks
#define PW      24              // words per row in x fp16 tile (conflict-free)
#define XTW     (64 * PW)       // words per x buffer

// W fragments: [chunk 0..31][step 0..1][wn 0..3][lane 0..31] -> uint4
//  .x/.y = b0/b1 of n-tile j=2*wn,  .z/.w = n-tile j=2*wn+1
__device__ uint4 g_wf[NCH * 2 * 4 * 32];   // 128 KB

__global__ void wconv(const float* __restrict__ W)
{
    int id   = blockIdx.x * blockDim.x + threadIdx.x;   // 0..8191
    int lane = id & 31;
    int wn   = (id >> 5) & 3;
    int st   = (id >> 7) & 1;
    int ch   = id >> 8;
    int s    = ch * 2 + st;
    int k    = s * 16 + (lane & 3) * 2;
    uint4 o;
#pragma unroll
    for (int jj = 0; jj < 2; jj++) {
        int n = (wn * 2 + jj) * 8 + (lane >> 2);
        const float* p = W + (size_t)n * NEMB + k;
        __half2 h0 = __float22half2_rn(make_float2(p[0], p[1]));
        __half2 h1 = __float22half2_rn(make_float2(p[8], p[9]));
        if (jj == 0) { o.x = *(uint32_t*)&h0; o.y = *(uint32_t*)&h1; }
        else         { o.z = *(uint32_t*)&h0; o.w = *(uint32_t*)&h1; }
    }
    g_wf[id] = o;
}

__shared__ __align__(16) uint4 wsm[4][2][4][32];     // 16 KB W ring (4 stages)
__shared__ __align__(16) unsigned int xsm[2 * XTW];  // 12 KB x fp16 tiles
__shared__ float bias_s[NH];

__device__ __forceinline__ void mma16816(float* c,
                                         uint32_t a0, uint32_t a1, uint32_t a2, uint32_t a3,
                                         uint32_t b0, uint32_t b1)
{
    asm volatile(
        "mma.sync.aligned.m16n8k16.row.col.f32.f16.f16.f32 "
        "{%0,%1,%2,%3}, {%4,%5,%6,%7}, {%8,%9}, {%0,%1,%2,%3};"
        : "+f"(c[0]), "+f"(c[1]), "+f"(c[2]), "+f"(c[3])
        : "r"(a0), "r"(a1), "r"(a2), "r"(a3), "r"(b0), "r"(b1));
}

__device__ __forceinline__ void cp16(uint32_t s, const void* g)
{
    asm volatile("cp.async.cg.shared.global [%0], [%1], 16;" :: "r"(s), "l"(g));
}

struct Ctx {
    const float* xg;       // this thread's x load pointer
    int convbase;          // STS word base
    int aoff;              // A-frag LDS word base
    int wn;                // warp N slice
    int lid;               // lane
    uint32_t wsm_s;        // smem addr of W ring
    int t;                 // thread id
};

// One chunk of work; BUF = c & 1, WST = c & 3 (compile-time).
template<int BUF, int WST>
__device__ __forceinline__ void chunk_body(const Ctx& cx, int c, float4& xr,
                                           float* acc0, float* acc1)
{
    // convert held x chunk -> fp16 tile buffer BUF
    {
        __half2 h0 = __float22half2_rn(make_float2(xr.x, xr.y));
        __half2 h1 = __float22half2_rn(make_float2(xr.z, xr.w));
        unsigned int* xb = xsm + BUF * XTW + cx.convbase;
        xb[0] = *(uint32_t*)&h0;
        xb[2] = *(uint32_t*)&h1;
    }

    // refill x ring (consumed again at c+4) and W ring stage for chunk c+3
    if (c + 4 < NCH)
        xr = *(const float4*)(cx.xg + (c + 4) * KCH);
    if (c + 3 < NCH && cx.t < 256)
        cp16(cx.wsm_s + (uint32_t)((((c + 3) & 3) * 256 + cx.t)) * 16,
             g_wf + (c + 3) * 256 + cx.t);
    asm volatile("cp.async.commit_group;");
    asm volatile("cp.async.wait_group 2;");
    __syncthreads();

    // compute: 2 k16-steps, 2 n-tiles
    const unsigned int* xb = xsm + BUF * XTW;
#pragma unroll
    for (int st = 0; st < 2; st++) {
        uint2 v0 = *(const uint2*)&xb[cx.aoff + st * 8];
        uint2 v1 = *(const uint2*)&xb[cx.aoff + st * 8 + 8 * PW];
        uint4 wq = wsm[WST][st][cx.wn][cx.lid];
        mma16816(acc0, v0.x, v1.x, v0.y, v1.y, wq.x, wq.y);
        mma16816(acc1, v0.x, v1.x, v0.y, v1.y, wq.z, wq.w);
    }
}

__global__ void __launch_bounds__(THREADS)
vproj(const float* __restrict__ x, const float* __restrict__ bv,
      float* __restrict__ out)
{
    const int t   = threadIdx.x;
    const int wid = t >> 5;
    const int lid = t & 31;
    const int wm  = wid & 3;          // M slice (16 rows)
    const int wn  = wid >> 2;         // N slice (16 cols)
    const int rowbase = blockIdx.x * MT;

    if (t < 16) ((float4*)bias_s)[t] = ((const float4*)bv)[t];

    Ctx cx;
    cx.wsm_s = (uint32_t)__cvta_generic_to_shared(&wsm[0][0][0][0]);
    cx.wn = wn; cx.lid = lid; cx.t = t;

    // x loader mapping: row = t>>3, q = t&7 (float4 within K32 chunk)
    const int lrow = t >> 3;
    const int q    = t & 7;
    cx.xg = x + (size_t)(rowbase + lrow) * NEMB + q * 4;

    const int qq   = q & 3;
    const int qst  = q >> 2;
    const int pos0 = (qq < 2) ? (qq * 4) : ((qq - 2) * 4 + 1);
    cx.convbase = lrow * PW + qst * 8 + pos0;
    cx.aoff = (wm * 16 + (lid >> 2)) * PW + (lid & 3) * 2;

    // prime: 4 x chunks in named registers, 3 W stages in flight
    float4 xr0 = *(const float4*)(cx.xg);
    float4 xr1 = *(const float4*)(cx.xg + KCH);
    float4 xr2 = *(const float4*)(cx.xg + 2 * KCH);
    float4 xr3 = *(const float4*)(cx.xg + 3 * KCH);

#pragma unroll
    for (int c = 0; c < 3; c++) {
        if (t < 256)
            cp16(cx.wsm_s + (uint32_t)(c * 256 + t) * 16, g_wf + c * 256 + t);
        asm volatile("cp.async.commit_group;");
    }

    float acc0[4] = {0.f, 0.f, 0.f, 0.f};
    float acc1[4] = {0.f, 0.f, 0.f, 0.f};

#pragma unroll 1
    for (int cc = 0; cc < NCH; cc += 4) {
        chunk_body<0, 0>(cx, cc + 0, xr0, acc0, acc1);
        chunk_body<1, 1>(cx, cc + 1, xr1, acc0, acc1);
        chunk_body<0, 2>(cx, cc + 2, xr2, acc0, acc1);
        chunk_body<1, 3>(cx, cc + 3, xr3, acc0, acc1);
    }

    // epilogue: add bias, store float2 pairs
    const int orow = rowbase + wm * 16 + (lid >> 2);
#pragma unroll
    for (int j = 0; j < 2; j++) {
        float* a = (j == 0) ? acc0 : acc1;
        const int col = (wn * 2 + j) * 8 + ((lid & 3) << 1);
        const float b0 = bias_s[col], b1 = bias_s[col + 1];
        float2 lo = make_float2(a[0] + b0, a[1] + b1);
        float2 hi = make_float2(a[2] + b0, a[3] + b1);
        *(float2*)(out + (size_t)orow * NH + col)       = lo;
        *(float2*)(out + (size_t)(orow + 8) * NH + col) = hi;
    }
}

extern "C" void kernel_launch(void* const* d_in, const int* in_sizes, int n_in,
                              void* d_out, int out_size)
{
    const float* x  = (const float*)d_in[0];
    const float* Wv = (const float*)d_in[5];
    const float* bv = (const float*)d_in[6];

    wconv<<<32, 256>>>(Wv);
    vproj<<<GRID, THREADS>>>(x, bv, (float*)d_out);
}

// round 9
// speedup vs baseline: 1.1969x; 1.1023x over previous
#include <cuda_runtime.h>
#include <cuda_fp16.h>
#include <cstdint>
#include <cstddef>

// out = x @ Wv^T + bv.  (Reference's softmax rows sum to 1 => its final
// einsum('btu,btj->btj', weights, v) == v + rounding; Q/K/softmax are dead.)
//
// Single-pass fp16 GEMM M=8192, K=1024, N=64 on portable mma.sync m16n8k16:
//   D = f16(x)*f16(W), fp32 accumulate; rel_err 2.92e-4 (measured) < 1e-3.
// R9 = R8 resubmitted after an infra-level container failure (kernel never
// ran; source audited clean). 8 fat K128 chunks (8 barriers), W fragments
// fully smem-resident (128 KB, cp.async'd once in prologue), 8 warps
// (4M x 2N, warp tile m16n32) for 2x register W reuse. All indices static.

#define NEMB    1024
#define NH      64
#define THREADS 256
#define GRID    128             // 8192 rows / 64 per CTA
#define KCH     128             // K per chunk
#define NCH     8
#define PW      24              // words per row per k32 sub-block (A-read conflict-free)
#define SUBW    1544            // words per sub-block (64*24 + 8 pad)
#define XBUFW   (4 * SUBW)      // words per x buffer (6176)
#define WSM_U4  8192            // W fragment uint4 count (64 steps * 4 * 32)
#define WSM_BYTES (WSM_U4 * 16)             // 131072
#define XSM_BYTES (2 * XBUFW * 4)           // 49408
#define SMEM_BYTES (WSM_BYTES + XSM_BYTES)  // 180480 (bias packed at tail of xsm pad? no: +0, bias below)

static_assert(WSM_BYTES == 131072, "wsm layout");
static_assert(XSM_BYTES == 49408, "xsm layout");
static_assert(SMEM_BYTES + 256 < 232448, "fits sm_103a smem");

// W fragments in gmem: id = ((s*2 + wn)*2 + p)*32 + lane
//   frags j = wn*4 + p*2 + {0,1};  n = j*8 + (lane>>2), k = s*16 + (lane&3)*2
//   .x = f16x2{W[n0][k],W[n0][k+1]}, .y = {W[n0][k+8],W[n0][k+9]}, .z/.w = n1
__device__ uint4 g_wf[WSM_U4];

__global__ void wconv(const float* __restrict__ W)
{
    int id   = blockIdx.x * blockDim.x + threadIdx.x;   // 0..8191
    int lane = id & 31;
    int p    = (id >> 5) & 1;
    int wn   = (id >> 6) & 1;
    int s    = id >> 7;
    int k    = s * 16 + (lane & 3) * 2;
    int j0   = wn * 4 + p * 2;
    uint4 o;
#pragma unroll
    for (int jj = 0; jj < 2; jj++) {
        int n = (j0 + jj) * 8 + (lane >> 2);
        const float* ptr = W + (size_t)n * NEMB + k;
        __half2 h0 = __float22half2_rn(make_float2(ptr[0], ptr[1]));
        __half2 h1 = __float22half2_rn(make_float2(ptr[8], ptr[9]));
        if (jj == 0) { o.x = *(uint32_t*)&h0; o.y = *(uint32_t*)&h1; }
        else         { o.z = *(uint32_t*)&h0; o.w = *(uint32_t*)&h1; }
    }
    g_wf[id] = o;
}

__device__ __forceinline__ void mma16816(float* c,
                                         uint32_t a0, uint32_t a1, uint32_t a2, uint32_t a3,
                                         uint32_t b0, uint32_t b1)
{
    asm volatile(
        "mma.sync.aligned.m16n8k16.row.col.f32.f16.f16.f32 "
        "{%0,%1,%2,%3}, {%4,%5,%6,%7}, {%8,%9}, {%0,%1,%2,%3};"
        : "+f"(c[0]), "+f"(c[1]), "+f"(c[2]), "+f"(c[3])
        : "r"(a0), "r"(a1), "r"(a2), "r"(a3), "r"(b0), "r"(b1));
}

__device__ __forceinline__ void cp16(uint32_t s, const void* g)
{
    asm volatile("cp.async.cg.shared.global [%0], [%1], 16;" :: "r"(s), "l"(g));
}

__device__ __forceinline__ uint32_t packh2(float a, float b)
{
    __half2 h = __float22half2_rn(make_float2(a, b));
    return *(uint32_t*)&h;
}

__shared__ float bias_s[NH];
extern __shared__ char smem[];

__global__ void __launch_bounds__(THREADS)
vproj(const float* __restrict__ x, const float* __restrict__ bv,
      float* __restrict__ out)
{
    const int t   = threadIdx.x;
    const int wid = t >> 5;
    const int lid = t & 31;
    const int wm  = wid & 3;          // M slice (16 rows)
    const int wn  = wid >> 2;         // N half (32 cols = 4 n-tiles)
    const int rowbase = blockIdx.x * 64;

    uint4*        wsm = (uint4*)smem;
    unsigned int* xsm = (unsigned int*)(smem + WSM_BYTES);

    if (t < 16) ((float4*)bias_s)[t] = ((const float4*)bv)[t];

    // ---- prologue: pull ALL W fragments into smem ----
    const uint32_t wsm_s = (uint32_t)__cvta_generic_to_shared(wsm);
#pragma unroll
    for (int i = 0; i < 32; i++)
        cp16(wsm_s + (uint32_t)(t + THREADS * i) * 16, g_wf + t + THREADS * i);
    asm volatile("cp.async.commit_group;");

    // x loader: row_t = t>>2 (0..63), sub_t = t&3 (k32 sub-block)
    const int row_t = t >> 2;
    const int sub_t = t & 3;
    const float* xg = x + (size_t)(rowbase + row_t) * NEMB + sub_t * 32;
    unsigned int* const xdst0 = xsm + sub_t * SUBW + row_t * PW;

    // chunk0 -> regs -> buf0
    float4 xr[8];
#pragma unroll
    for (int q = 0; q < 8; q++) xr[q] = *(const float4*)(xg + q * 4);

    // convert: word layout per row = interleaved pairs (A-frag reads uint2 at
    // {0,2,4,6} + st*8; group gg covers words 4gg..4gg+3)
#define CONV_GROUP(dst, gg, qa, qb)                                     \
    {                                                                   \
        uint4 u;                                                        \
        u.x = packh2(xr[qa].x, xr[qa].y);                               \
        u.y = packh2(xr[qb].x, xr[qb].y);                               \
        u.z = packh2(xr[qa].z, xr[qa].w);                               \
        u.w = packh2(xr[qb].z, xr[qb].w);                               \
        *(uint4*)((dst) + (gg) * 4) = u;                                \
    }
#define CONV_ALL(dst) \
    CONV_GROUP(dst, 0, 0, 2) CONV_GROUP(dst, 1, 1, 3) \
    CONV_GROUP(dst, 2, 4, 6) CONV_GROUP(dst, 3, 5, 7)

    CONV_ALL(xdst0)
    asm volatile("cp.async.wait_group 0;");
    __syncthreads();

    float acc[4][4];
#pragma unroll
    for (int j = 0; j < 4; j++)
#pragma unroll
        for (int e = 0; e < 4; e++) acc[j][e] = 0.0f;

    // A-frag word offset within a sub-block (conflict-free: rows {0,24,16,8}+{0,2,4,6})
    const int aoffw = (wm * 16 + (lid >> 2)) * PW + (lid & 3) * 2;
    const int wbase = wn * 64 + lid;   // uint4 index base for W LDS.128

#pragma unroll
    for (int c = 0; c < NCH; c++) {
        // issue next chunk's LDGs first (one full phase of latency cover)
        if (c + 1 < NCH) {
#pragma unroll
            for (int q = 0; q < 8; q++)
                xr[q] = *(const float4*)(xg + (c + 1) * KCH + q * 4);
        }

        // compute 8 k16-steps from buf c&1 + resident W
        const unsigned int* xb = xsm + (c & 1) * XBUFW;
#pragma unroll
        for (int stp = 0; stp < 8; stp++) {
            const int sub = stp >> 1, st = stp & 1;
            const unsigned int* ap = xb + sub * SUBW + aoffw + st * 8;
            uint2 v0 = *(const uint2*)ap;
            uint2 v1 = *(const uint2*)(ap + 8 * PW);
            const int sg = c * 8 + stp;
            uint4 w0 = wsm[sg * 128 + wbase];
            uint4 w1 = wsm[sg * 128 + wbase + 32];
            mma16816(acc[0], v0.x, v1.x, v0.y, v1.y, w0.x, w0.y);
            mma16816(acc[1], v0.x, v1.x, v0.y, v1.y, w0.z, w0.w);
            mma16816(acc[2], v0.x, v1.x, v0.y, v1.y, w1.x, w1.y);
            mma16816(acc[3], v0.x, v1.x, v0.y, v1.y, w1.z, w1.w);
        }

        // convert next chunk into the other buffer
        if (c + 1 < NCH) {
            unsigned int* dst = xsm + ((c + 1) & 1) * XBUFW + sub_t * SUBW + row_t * PW;
            CONV_ALL(dst)
            __syncthreads();
        }
    }

    // ---- epilogue: add bias, store float2 pairs ----
    const int orow = rowbase + wm * 16 + (lid >> 2);
#pragma unroll
    for (int j = 0; j < 4; j++) {
        const int col = wn * 32 + j * 8 + ((lid & 3) << 1);
        const float b0 = bias_s[col], b1 = bias_s[col + 1];
        float2 lo = make_float2(acc[j][0] + b0, acc[j][1] + b1);
        float2 hi = make_float2(acc[j][2] + b0, acc[j][3] + b1);
        *(float2*)(out + (size_t)orow * NH + col)       = lo;
        *(float2*)(out + (size_t)(orow + 8) * NH + col) = hi;
    }
#undef CONV_ALL
#undef CONV_GROUP
}

extern "C" void kernel_launch(void* const* d_in, const int* in_sizes, int n_in,
                              void* d_out, int out_size)
{
    const float* x  = (const float*)d_in[0];
    const float* Wv = (const float*)d_in[5];
    const float* bv = (const float*)d_in[6];

    cudaFuncSetAttribute(vproj, cudaFuncAttributeMaxDynamicSharedMemorySize, SMEM_BYTES);
    wconv<<<32, 256>>>(Wv);
    vproj<<<GRID, THREADS, SMEM_BYTES>>>(x, bv, (float*)d_out);
}

// round 11
// speedup vs baseline: 1.4848x; 1.2405x over previous
#include <cuda_runtime.h>
#include <cuda_fp16.h>
#include <cstdint>
#include <cstddef>

// out = x @ Wv^T + bv.  (Reference's softmax rows sum to 1 => its final
// einsum('btu,btj->btj', weights, v) == v + rounding; Q/K/softmax are dead.)
//
// Single-pass fp16 GEMM M=8192, K=1024, N=64 on portable mma.sync m16n8k16:
//   D = f16(x)*f16(W), fp32 accumulate; rel_err 2.92e-4 (measured) < 1e-3.
// R10 = R9 skeleton (8 fat K128 chunks, W fragments smem-resident) with:
//   * 512 threads / 16 warps: K-SPLIT warp doubling (kh=0 -> steps 0-3,
//     kh=1 -> steps 4-7 of each chunk) => 4 warps/SMSP, half chain per warp.
//   * explicit 2-stage fragment pipelining inside the step loop.
//   * smem K-reduction epilogue (stride-20 padded, conflict-free).

#define NEMB    1024
#define NH      64
#define THREADS 512
#define GRID    128             // 8192 rows / 64 per CTA
#define KCH     128             // K per chunk
#define NCH     8
#define PW      24              // words per row per k32 sub-block
#define SUBW    1544            // words per sub-block (64*24 + 8 pad)
#define XBUFW   (4 * SUBW)      // words per x buffer (6176)
#define WSM_U4  8192            // W fragment uint4 count
#define WSM_BYTES (WSM_U4 * 16)             // 131072
#define XSM_BYTES (2 * XBUFW * 4)           // 49408
#define SMEM_BYTES (WSM_BYTES + XSM_BYTES)  // 180480

static_assert(SMEM_BYTES < 227000, "fits sm_103a smem");

// W fragments in gmem: id = ((s*2 + wn)*2 + p)*32 + lane  (same as R9)
__device__ uint4 g_wf[WSM_U4];

__global__ void wconv(const float* __restrict__ W)
{
    int id   = blockIdx.x * blockDim.x + threadIdx.x;   // 0..8191
    int lane = id & 31;
    int p    = (id >> 5) & 1;
    int wn   = (id >> 6) & 1;
    int s    = id >> 7;
    int k    = s * 16 + (lane & 3) * 2;
    int j0   = wn * 4 + p * 2;
    uint4 o;
#pragma unroll
    for (int jj = 0; jj < 2; jj++) {
        int n = (j0 + jj) * 8 + (lane >> 2);
        const float* ptr = W + (size_t)n * NEMB + k;
        __half2 h0 = __float22half2_rn(make_float2(ptr[0], ptr[1]));
        __half2 h1 = __float22half2_rn(make_float2(ptr[8], ptr[9]));
        if (jj == 0) { o.x = *(uint32_t*)&h0; o.y = *(uint32_t*)&h1; }
        else         { o.z = *(uint32_t*)&h0; o.w = *(uint32_t*)&h1; }
    }
    g_wf[id] = o;
}

__device__ __forceinline__ void mma16816(float* c,
                                         uint32_t a0, uint32_t a1, uint32_t a2, uint32_t a3,
                                         uint32_t b0, uint32_t b1)
{
    asm volatile(
        "mma.sync.aligned.m16n8k16.row.col.f32.f16.f16.f32 "
        "{%0,%1,%2,%3}, {%4,%5,%6,%7}, {%8,%9}, {%0,%1,%2,%3};"
        : "+f"(c[0]), "+f"(c[1]), "+f"(c[2]), "+f"(c[3])
        : "r"(a0), "r"(a1), "r"(a2), "r"(a3), "r"(b0), "r"(b1));
}

__device__ __forceinline__ void cp16(uint32_t s, const void* g)
{
    asm volatile("cp.async.cg.shared.global [%0], [%1], 16;" :: "r"(s), "l"(g));
}

__device__ __forceinline__ uint32_t packh2(float a, float b)
{
    __half2 h = __float22half2_rn(make_float2(a, b));
    return *(uint32_t*)&h;
}

__shared__ float bias_s[NH];
extern __shared__ char smem[];

__global__ void __launch_bounds__(THREADS)
vproj(const float* __restrict__ x, const float* __restrict__ bv,
      float* __restrict__ out)
{
    const int t   = threadIdx.x;
    const int wid = t >> 5;
    const int lid = t & 31;
    const int kh  = wid >> 3;         // K half: 0 -> steps 0-3, 1 -> steps 4-7
    const int w8  = wid & 7;
    const int wm  = w8 & 3;           // M slice (16 rows)
    const int wn  = w8 >> 2;          // N half (32 cols)
    const int rowbase = blockIdx.x * 64;

    uint4*        wsm = (uint4*)smem;
    unsigned int* xsm = (unsigned int*)(smem + WSM_BYTES);

    if (t < 16) ((float4*)bias_s)[t] = ((const float4*)bv)[t];

    // ---- prologue: pull ALL W fragments into smem ----
    const uint32_t wsm_s = (uint32_t)__cvta_generic_to_shared(wsm);
#pragma unroll
    for (int i = 0; i < 16; i++)
        cp16(wsm_s + (uint32_t)(t + THREADS * i) * 16, g_wf + t + THREADS * i);
    asm volatile("cp.async.commit_group;");

    // x loader: row_t = t>>3 (0..63), sub_t = (t>>1)&3, half = t&1
    const int row_t = t >> 3;
    const int sub_t = (t >> 1) & 3;
    const int half  = t & 1;
    const float* xg = x + (size_t)(rowbase + row_t) * NEMB + sub_t * 32 + half * 16;

    float4 xr[4];
#pragma unroll
    for (int q = 0; q < 4; q++) xr[q] = *(const float4*)(xg + q * 4);

    // convert: half=0 writes words 0..7, half=1 words 8..15 of the row
#define CONV_ALL(dst)                                                   \
    {                                                                   \
        uint4 u;                                                        \
        u.x = packh2(xr[0].x, xr[0].y);                                 \
        u.y = packh2(xr[2].x, xr[2].y);                                 \
        u.z = packh2(xr[0].z, xr[0].w);                                 \
        u.w = packh2(xr[2].z, xr[2].w);                                 \
        *(uint4*)((dst)) = u;                                           \
        u.x = packh2(xr[1].x, xr[1].y);                                 \
        u.y = packh2(xr[3].x, xr[3].y);                                 \
        u.z = packh2(xr[1].z, xr[1].w);                                 \
        u.w = packh2(xr[3].z, xr[3].w);                                 \
        *(uint4*)((dst) + 4) = u;                                       \
    }

    unsigned int* const xdst0 = xsm + sub_t * SUBW + row_t * PW + half * 8;
    CONV_ALL(xdst0)
    asm volatile("cp.async.wait_group 0;");
    __syncthreads();

    float acc[4][4];
#pragma unroll
    for (int j = 0; j < 4; j++)
#pragma unroll
        for (int e = 0; e < 4; e++) acc[j][e] = 0.0f;

    const int aoffw = (wm * 16 + (lid >> 2)) * PW + (lid & 3) * 2;
    const int wbase = wn * 64 + lid;

    // fragment loader for k16-step `stp` of chunk c (addresses runtime, slots static)
#define LOAD_FRAGS(slot, xb, c, stp)                                    \
    {                                                                   \
        const int sub_ = (stp) >> 1, st_ = (stp) & 1;                   \
        const unsigned int* ap = (xb) + sub_ * SUBW + aoffw + st_ * 8;  \
        av0[slot] = *(const uint2*)ap;                                  \
        av1[slot] = *(const uint2*)(ap + 8 * PW);                       \
        const int sg = (c) * 8 + (stp);                                 \
        wq0[slot] = wsm[sg * 128 + wbase];                              \
        wq1[slot] = wsm[sg * 128 + wbase + 32];                         \
    }
#define DO_MMAS(slot)                                                   \
    {                                                                   \
        mma16816(acc[0], av0[slot].x, av1[slot].x, av0[slot].y, av1[slot].y, wq0[slot].x, wq0[slot].y); \
        mma16816(acc[1], av0[slot].x, av1[slot].x, av0[slot].y, av1[slot].y, wq0[slot].z, wq0[slot].w); \
        mma16816(acc[2], av0[slot].x, av1[slot].x, av0[slot].y, av1[slot].y, wq1[slot].x, wq1[slot].y); \
        mma16816(acc[3], av0[slot].x, av1[slot].x, av0[slot].y, av1[slot].y, wq1[slot].z, wq1[slot].w); \
    }

#pragma unroll
    for (int c = 0; c < NCH; c++) {
        // next chunk's LDGs first (one full phase of latency cover)
        if (c + 1 < NCH) {
#pragma unroll
            for (int q = 0; q < 4; q++)
                xr[q] = *(const float4*)(xg + (c + 1) * KCH + q * 4);
        }

        // compute this warp's 4 k16-steps, 2-stage pipelined
        {
            const unsigned int* xb = xsm + (c & 1) * XBUFW;
            uint2 av0[2], av1[2];
            uint4 wq0[2], wq1[2];
            LOAD_FRAGS(0, xb, c, kh * 4 + 0)
#pragma unroll
            for (int sl = 0; sl < 4; sl++) {
                if (sl < 3) {
                    if ((sl & 1) == 0) LOAD_FRAGS(1, xb, c, kh * 4 + sl + 1)
                    else               LOAD_FRAGS(0, xb, c, kh * 4 + sl + 1)
                }
                if ((sl & 1) == 0) DO_MMAS(0)
                else               DO_MMAS(1)
            }
        }

        // convert next chunk into the other buffer
        if (c + 1 < NCH) {
            unsigned int* dst = xsm + ((c + 1) & 1) * XBUFW
                              + sub_t * SUBW + row_t * PW + half * 8;
            CONV_ALL(dst)
            __syncthreads();
        }
    }

    // ---- K-reduction + epilogue ----
    // kh=1 warps park accs in smem (buffer 0 region, stride 20: conflict-free)
    float* red = (float*)xsm;
    const int rbase = ((w8 * 32) + lid) * 20;
    __syncthreads();
    if (kh == 1) {
#pragma unroll
        for (int j = 0; j < 4; j++)
            *(float4*)(red + rbase + j * 4) = *(float4*)acc[j];
    }
    __syncthreads();
    if (kh == 0) {
        const int orow = rowbase + wm * 16 + (lid >> 2);
#pragma unroll
        for (int j = 0; j < 4; j++) {
            float4 o = *(float4*)(red + rbase + j * 4);
            const int col = wn * 32 + j * 8 + ((lid & 3) << 1);
            const float b0 = bias_s[col], b1 = bias_s[col + 1];
            float2 lo = make_float2(acc[j][0] + o.x + b0, acc[j][1] + o.y + b1);
            float2 hi = make_float2(acc[j][2] + o.z + b0, acc[j][3] + o.w + b1);
            *(float2*)(out + (size_t)orow * NH + col)       = lo;
            *(float2*)(out + (size_t)(orow + 8) * NH + col) = hi;
        }
    }
#undef CONV_ALL
#undef LOAD_FRAGS
#undef DO_MMAS
}

extern "C" void kernel_launch(void* const* d_in, const int* in_sizes, int n_in,
                              void* d_out, int out_size)
{
    const float* x  = (const float*)d_in[0];
    const float* Wv = (const float*)d_in[5];
    const float* bv = (const float*)d_in[6];

    cudaFuncSetAttribute(vproj, cudaFuncAttributeMaxDynamicSharedMemorySize, SMEM_BYTES);
    wconv<<<32, 256>>>(Wv);
    vproj<<<GRID, THREADS, SMEM_BYTES>>>(x, bv, (float*)d_out);
}